// round 2
// baseline (speedup 1.0000x reference)
#include <cuda_runtime.h>
#include <cuda_bf16.h>

#define DEPTH     4096
#define NTHREADS  512
#define HKC       0.70710678118654752440f  /* 1/sqrt(2) */

// Fully fused wavelet layer: one CTA per row (8192 rows x 4096 f32).
//   y   = x * vec_b                      (fused into global load + scale-1)
//   c   = haar_wavedec(y), 4 scales      (smem ping-pong)
//   g   = c[perm] * vec_g                (smem gather)
//   out = haar_waverec(overlapping slices of g) * vec_s  (fused into store)
//
// Reference slice map (reproduced exactly, incl. overlapping slices):
//   coeff_lst = [ g[0:256], g[2048:2304], g[1024:1536], g[512:1536], g[256:2304] ]
__global__ __launch_bounds__(NTHREADS)
void wavelet_fused_kernel(const float* __restrict__ x,
                          const float* __restrict__ vec_b,
                          const float* __restrict__ vec_g,
                          const float* __restrict__ vec_s,
                          const int*  __restrict__ perm,
                          float* __restrict__ out)
{
    __shared__ float sA[DEPTH];        // 16 KB  (gathered coeffs g)
    __shared__ float sB[DEPTH];        // 16 KB  (wavedec output c)
    __shared__ float sC[DEPTH / 2];    //  8 KB  (ping buffer)

    const int row = blockIdx.x;
    const int tid = threadIdx.x;

    // ---- load x*vec_b and compute wavedec scale 1 directly in registers --
    // Each float4 = 2 Haar pairs:  cA -> sC[0:2048], cD1 -> sB[2048:4096]
    {
        const float4* x4 = reinterpret_cast<const float4*>(x + (size_t)row * DEPTH);
        const float4* b4 = reinterpret_cast<const float4*>(vec_b);
        float2* cA2 = reinterpret_cast<float2*>(sC);
        float2* cD2 = reinterpret_cast<float2*>(sB + 2048);
        #pragma unroll
        for (int j = 0; j < (DEPTH / 4) / NTHREADS; ++j) {   // 2 iters
            int i = tid + j * NTHREADS;
            float4 xv = __ldcs(&x4[i]);                      // streaming read
            float4 bv = __ldg(&b4[i]);
            float y0 = xv.x * bv.x, y1 = xv.y * bv.y;
            float y2 = xv.z * bv.z, y3 = xv.w * bv.w;
            float2 a, d;
            a.x = (y0 + y1) * HKC;  a.y = (y2 + y3) * HKC;
            d.x = (y0 - y1) * HKC;  d.y = (y2 - y3) * HKC;
            cA2[i] = a;
            cD2[i] = d;
        }
    }
    __syncthreads();

    // ---- scale 2: sC[0:2048] -> cA sA[0:1024], cD2 sB[1024:2048] ---------
    {
        const float2* in2 = reinterpret_cast<const float2*>(sC);
        #pragma unroll
        for (int j = 0; j < 1024 / NTHREADS; ++j) {          // 2 iters
            int i = tid + j * NTHREADS;
            float2 p = in2[i];
            sA[i]        = (p.x + p.y) * HKC;
            sB[1024 + i] = (p.x - p.y) * HKC;
        }
    }
    __syncthreads();

    // ---- scale 3: sA[0:1024] -> cA sC[0:512], cD3 sB[512:1024] -----------
    {
        float2 p = reinterpret_cast<const float2*>(sA)[tid]; // tid < 512
        sC[tid]       = (p.x + p.y) * HKC;
        sB[512 + tid] = (p.x - p.y) * HKC;
    }
    __syncthreads();

    // ---- scale 4: sC[0:512] -> cA4 sB[0:256], cD4 sB[256:512] ------------
    if (tid < 256) {
        float2 p = reinterpret_cast<const float2*>(sC)[tid];
        sB[tid]       = (p.x + p.y) * HKC;
        sB[256 + tid] = (p.x - p.y) * HKC;
    }
    __syncthreads();

    // sB = c = [cA4(256) | d4(256) | d3(512) | d2(1024) | d1(2048)]

    // ---- permutation gather + vec_g:  sA[i] = sB[perm[i]] * vec_g[i] -----
    #pragma unroll
    for (int j = 0; j < DEPTH / NTHREADS; ++j) {             // 8 iters
        int i = tid + j * NTHREADS;
        int p = __ldg(&perm[i]);
        sA[i] = sB[p] * __ldg(&vec_g[i]);
    }
    __syncthreads();

    // ---- rec step 1: cA = sA[0:256], cD = sA[2048:2304] -> r1[512] in sC -
    if (tid < 256) {
        float a = sA[tid], d = sA[2048 + tid];
        float2 r; r.x = (a + d) * HKC; r.y = (a - d) * HKC;
        reinterpret_cast<float2*>(sC)[tid] = r;
    }
    __syncthreads();

    // ---- rec step 2: cA = sC[0:512], cD = sA[1024:1536] -> r2[1024] in sB
    {
        float a = sC[tid], d = sA[1024 + tid];               // tid < 512
        float2 r; r.x = (a + d) * HKC; r.y = (a - d) * HKC;
        reinterpret_cast<float2*>(sB)[tid] = r;
    }
    __syncthreads();

    // ---- rec step 3: cA = sB[0:1024], cD = sA[512:1536] -> r3[2048] in sC
    #pragma unroll
    for (int j = 0; j < 1024 / NTHREADS; ++j) {              // 2 iters
        int i = tid + j * NTHREADS;
        float a = sB[i], d = sA[512 + i];
        float2 r; r.x = (a + d) * HKC; r.y = (a - d) * HKC;
        reinterpret_cast<float2*>(sC)[i] = r;
    }
    __syncthreads();

    // ---- rec step 4 + vec_s + streaming store ----------------------------
    //      cA = sC[0:2048], cD = sA[256:2304]
    {
        float2* out2 = reinterpret_cast<float2*>(out + (size_t)row * DEPTH);
        const float2* s2 = reinterpret_cast<const float2*>(vec_s);
        #pragma unroll
        for (int j = 0; j < 2048 / NTHREADS; ++j) {          // 4 iters
            int i = tid + j * NTHREADS;
            float a = sC[i], d = sA[256 + i];
            float2 sv = __ldg(&s2[i]);
            float2 r;
            r.x = (a + d) * HKC * sv.x;
            r.y = (a - d) * HKC * sv.y;
            __stcs(&out2[i], r);                             // streaming write
        }
    }
}

extern "C" void kernel_launch(void* const* d_in, const int* in_sizes, int n_in,
                              void* d_out, int out_size)
{
    const float* x     = (const float*)d_in[0];
    const float* vec_b = (const float*)d_in[1];
    const float* vec_g = (const float*)d_in[2];
    const float* vec_s = (const float*)d_in[3];
    const int*   perm  = (const int*)  d_in[4];
    float* out = (float*)d_out;

    const int batch = in_sizes[0] / DEPTH;   // 8192
    wavelet_fused_kernel<<<batch, NTHREADS>>>(x, vec_b, vec_g, vec_s, perm, out);
}